// round 4
// baseline (speedup 1.0000x reference)
#include <cuda_runtime.h>
#include <cstdint>
#include <cstddef>

// Problem constants
#define Bq 8
#define Nq 2048
#define Kq 32
#define Fq 256          // F_IN = F_OUT = 256
#define Cq 512          // 2*F_OUT
#define Mq (Bq*Nq)      // 16384 rows

// Scratch (no cudaMalloc allowed)
__device__ float g_xn[(size_t)Mq * Fq];   // gathered neighbor means, 16 MB
__device__ float g_sum[Cq];
__device__ float g_sumsq[Cq];
__device__ float4 g_scale4[Cq / 4];
__device__ float4 g_shift4[Cq / 4];

typedef unsigned long long u64;
typedef unsigned int u32;

__device__ __forceinline__ u64 ffma2(u64 a, u64 b, u64 c) {
    u64 d;
    asm("fma.rn.f32x2 %0, %1, %2, %3;" : "=l"(d) : "l"(a), "l"(b), "l"(c));
    return d;
}
__device__ __forceinline__ void cpa4(u32 dst, const void* src) {
    asm volatile("cp.async.ca.shared.global [%0], [%1], 4;" :: "r"(dst), "l"(src));
}
#define CP_COMMIT() asm volatile("cp.async.commit_group;")
#define CP_WAIT(n)  asm volatile("cp.async.wait_group %0;" :: "n"(n))

// ---------------------------------------------------------------------------
// Kernel 1: gather + mean over 32 neighbors. 4 rows/block, 64 f4-lanes/row.
// Block 0 also zeroes the BN stat accumulators (ALL 512 channels).
// ---------------------------------------------------------------------------
__global__ __launch_bounds__(256) void k_gather(const float4* __restrict__ x4,
                                                const int* __restrict__ idx,
                                                float4* __restrict__ xn4) {
    if (blockIdx.x == 0) {
        const int c = threadIdx.x;          // 256 threads -> 2 entries each
        g_sum[c] = 0.f;         g_sum[c + 256] = 0.f;
        g_sumsq[c] = 0.f;       g_sumsq[c + 256] = 0.f;
    }
    __shared__ int nbr[4][Kq];
    const int tid = threadIdx.x;
    const int rr = tid >> 6;          // row within block, 0..3
    const int q  = tid & 63;          // float4 lane within row
    const int r  = blockIdx.x * 4 + rr;   // global row = b*N + n
    const int b  = r >> 11;           // N = 2048

    if (tid < 128) {
        int k   = tid & 31;
        int rr2 = tid >> 5;
        int n2  = (blockIdx.x * 4 + rr2) & (Nq - 1);
        nbr[rr2][k] = idx[n2 * Kq + k];
    }
    __syncthreads();

    const float4* xb = x4 + (size_t)b * Nq * (Fq / 4);
    float4 acc = make_float4(0.f, 0.f, 0.f, 0.f);
#pragma unroll
    for (int k = 0; k < Kq; k++) {
        float4 v = xb[(size_t)nbr[rr][k] * (Fq / 4) + q];
        acc.x += v.x; acc.y += v.y; acc.z += v.z; acc.w += v.w;
    }
    const float s = 1.f / 32.f;
    acc.x *= s; acc.y *= s; acc.z *= s; acc.w *= s;
    xn4[(size_t)r * (Fq / 4) + q] = acc;
}

// ---------------------------------------------------------------------------
// Kernel 2: dual GEMM (packed f32x2: .x = self, .y = neighbor) + bias
//           + per-row L2 normalize + ReLU + write out + BN stat accumulation.
// Block tile: 64 rows x 256 channel-pairs. 512 threads = 16 warps.
// Warp w: rows (w&7)*8..+8, channel half (w>>3).
// Per thread: 8 rows x 4 pairs in registers (64 acc regs).
// Double-buffered cp.async tile pipeline; W stored channel-major for LDS.128.
// ---------------------------------------------------------------------------
#define MT 64
#define KT 32
#define KP 34          // float2 pitch over kk (lane stride 68 words = 4 mod 32)
#define WTILE (256 * KP)   // float2 count of one W tile
#define XTILE (MT * KP)    // float2 count of one X tile
#define SMEM2 ((size_t)(2*WTILE + 2*XTILE + 2*256) * sizeof(float2) + (MT*2) * sizeof(float))

__global__ __launch_bounds__(512, 1) void k_gemm(const float* __restrict__ x,
                                                 const float* __restrict__ Wx,
                                                 const float* __restrict__ Wn,
                                                 const float* __restrict__ bx,
                                                 const float* __restrict__ bn,
                                                 float* __restrict__ out) {
    extern __shared__ char smem_raw[];
    float2* sW0  = (float2*)smem_raw;                         // [256][KP]
    float2* sW1  = sW0 + WTILE;
    float2* sX0  = sW1 + WTILE;                               // [MT][KP]
    float2* sX1  = sX0 + XTILE;
    float2* redS = sX1 + XTILE;                               // [256]
    float2* redQ = redS + 256;                                // [256]
    float*  ssb  = (float*)(redQ + 256);                      // [MT][2]

    const u32 sm_base = (u32)__cvta_generic_to_shared(smem_raw);
    const u32 uW[2] = { sm_base, sm_base + WTILE * 8 };
    const u32 uX[2] = { sm_base + 2 * WTILE * 8, sm_base + (2 * WTILE + XTILE) * 8 };
    float2* const pW[2] = { sW0, sW1 };
    float2* const pX[2] = { sX0, sX1 };

    const int tid  = threadIdx.x;
    const int lane = tid & 31;
    const int w    = tid >> 5;                 // warp id 0..15
    const int wr   = w & 7;                    // row group
    const int wh   = w >> 3;                   // channel half
    const int row0 = blockIdx.x * MT;

    if (tid < 256) {
        redS[tid] = make_float2(0.f, 0.f);
        redQ[tid] = make_float2(0.f, 0.f);
    }

    const float* xrow  = x    + (size_t)row0 * Fq;
    const float* xnrow = g_xn + (size_t)row0 * Fq;
    const int cbase = lane + 128 * wh;         // channel of pair j=0

    const int lk = tid & 31;                   // this thread's k within tile
    const int lg = tid >> 5;                   // 0..15

    // Issue async loads of tile t into buffer buf.
    auto issue = [&](int t, int buf) {
        const int k0 = t * KT;
#pragma unroll
        for (int i = 0; i < 16; i++) {
            const int c = lg + 16 * i;
            const u32 d = uW[buf] + (u32)(c * KP + lk) * 8;
            cpa4(d,     Wx + c * Fq + k0 + lk);
            cpa4(d + 4, Wn + c * Fq + k0 + lk);
        }
#pragma unroll
        for (int i = 0; i < 4; i++) {
            const int m = lg + 16 * i;
            const u32 d = uX[buf] + (u32)(m * KP + lk) * 8;
            cpa4(d,     xrow  + (size_t)m * Fq + k0 + lk);
            cpa4(d + 4, xnrow + (size_t)m * Fq + k0 + lk);
        }
    };

    u64 acc[8][4];
#pragma unroll
    for (int i = 0; i < 8; i++)
#pragma unroll
        for (int j = 0; j < 4; j++) acc[i][j] = 0ull;

    issue(0, 0); CP_COMMIT();
    issue(1, 1); CP_COMMIT();

    for (int t = 0; t < Fq / KT; t++) {
        if (t < Fq / KT - 1) CP_WAIT(1); else CP_WAIT(0);
        __syncthreads();

        const float2* cw = pW[t & 1];
        const float2* cx = pX[t & 1];

#pragma unroll 2
        for (int kk = 0; kk < KT; kk += 2) {
            float4 b4[4];
#pragma unroll
            for (int j = 0; j < 4; j++)
                b4[j] = *(const float4*)(cw + (cbase + 32 * j) * KP + kk);
#pragma unroll
            for (int h = 0; h < 2; h++) {
                float4 a4[4];
#pragma unroll
                for (int i = 0; i < 4; i++)
                    a4[i] = *(const float4*)(cx + (wr * 8 + h * 4 + i) * KP + kk);
#pragma unroll
                for (int i = 0; i < 4; i++) {
                    const u64 alo = ((const u64*)&a4[i])[0];
                    const u64 ahi = ((const u64*)&a4[i])[1];
#pragma unroll
                    for (int j = 0; j < 4; j++) {
                        const u64 blo = ((const u64*)&b4[j])[0];
                        const u64 bhi = ((const u64*)&b4[j])[1];
                        acc[h * 4 + i][j] = ffma2(alo, blo, acc[h * 4 + i][j]);
                        acc[h * 4 + i][j] = ffma2(ahi, bhi, acc[h * 4 + i][j]);
                    }
                }
            }
        }

        if (t < Fq / KT - 2) {
            __syncthreads();            // everyone done reading buf t&1
            issue(t + 2, t & 1); CP_COMMIT();
        }
    }

    // ---- Epilogue ----
    float2 bias[4];
#pragma unroll
    for (int j = 0; j < 4; j++)
        bias[j] = make_float2(bx[cbase + 32 * j], bn[cbase + 32 * j]);

    // Phase 1: bias + per-row partial sum of squares (this warp's 128 pairs)
    float2 v[8][4];
#pragma unroll
    for (int i = 0; i < 8; i++) {
        float ss = 0.f;
#pragma unroll
        for (int j = 0; j < 4; j++) {
            v[i][j] = *(float2*)&acc[i][j];
            v[i][j].x += bias[j].x;
            v[i][j].y += bias[j].y;
            ss += v[i][j].x * v[i][j].x + v[i][j].y * v[i][j].y;
        }
#pragma unroll
        for (int off = 16; off > 0; off >>= 1)
            ss += __shfl_xor_sync(0xffffffffu, ss, off);
        if (lane == 0) ssb[(wr * 8 + i) * 2 + wh] = ss;
    }
    __syncthreads();

    // Phase 2: normalize, relu, store, accumulate stats
    float2 ps[4], pq[4];
#pragma unroll
    for (int j = 0; j < 4; j++) {
        ps[j] = make_float2(0.f, 0.f);
        pq[j] = make_float2(0.f, 0.f);
    }
#pragma unroll
    for (int i = 0; i < 8; i++) {
        const int mr = wr * 8 + i;
        const float sstot = ssb[mr * 2] + ssb[mr * 2 + 1];
        const float rn = 1.f / fmaxf(sqrtf(sstot), 1e-12f);
        float* orow = out + (size_t)(row0 + mr) * Cq;
#pragma unroll
        for (int j = 0; j < 4; j++) {
            float hx = fmaxf(v[i][j].x * rn, 0.f);
            float hn = fmaxf(v[i][j].y * rn, 0.f);
            orow[cbase + 32 * j]       = hx;
            orow[256 + cbase + 32 * j] = hn;
            ps[j].x += hx;      ps[j].y += hn;
            pq[j].x += hx * hx; pq[j].y += hn * hn;
        }
    }

#pragma unroll
    for (int j = 0; j < 4; j++) {
        const int c = cbase + 32 * j;
        atomicAdd(&redS[c].x, ps[j].x);
        atomicAdd(&redS[c].y, ps[j].y);
        atomicAdd(&redQ[c].x, pq[j].x);
        atomicAdd(&redQ[c].y, pq[j].y);
    }
    __syncthreads();
    if (tid < 256) {
        atomicAdd(&g_sum[tid],         redS[tid].x);
        atomicAdd(&g_sum[tid + 256],   redS[tid].y);
        atomicAdd(&g_sumsq[tid],       redQ[tid].x);
        atomicAdd(&g_sumsq[tid + 256], redQ[tid].y);
    }
}

// ---------------------------------------------------------------------------
// Kernel 3: fold BN stats into per-channel scale/shift.
// ---------------------------------------------------------------------------
__global__ void k_stats(const float* __restrict__ gamma,
                        const float* __restrict__ beta) {
    const int c = threadIdx.x;   // 512 threads
    const float inv_n = 1.f / (float)Mq;
    float mu  = g_sum[c] * inv_n;
    float var = fmaxf(g_sumsq[c] * inv_n - mu * mu, 0.f);
    float inv = rsqrtf(var + 1e-5f);
    float sc  = gamma[c] * inv;
    ((float*)g_scale4)[c] = sc;
    ((float*)g_shift4)[c] = beta[c] - mu * sc;
}

// ---------------------------------------------------------------------------
// Kernel 4: apply BN elementwise in place. 2 float4 per thread, half-grid
// apart (same channel slot -> shared scale/shift regs).
// ---------------------------------------------------------------------------
#define HALF4 ((size_t)Mq * (Cq / 4) / 2)    // float4 count of half the output
__global__ __launch_bounds__(256) void k_apply(float4* __restrict__ out4) {
    const size_t i = (size_t)blockIdx.x * blockDim.x + threadIdx.x;
    const int p = (int)(i & 127);         // float4 index within 512-ch row
    const float4 sc = g_scale4[p];
    const float4 sh = g_shift4[p];
    float4 v1 = out4[i];
    float4 v2 = out4[i + HALF4];
    v1.x = v1.x * sc.x + sh.x;  v1.y = v1.y * sc.y + sh.y;
    v1.z = v1.z * sc.z + sh.z;  v1.w = v1.w * sc.w + sh.w;
    v2.x = v2.x * sc.x + sh.x;  v2.y = v2.y * sc.y + sh.y;
    v2.z = v2.z * sc.z + sh.z;  v2.w = v2.w * sc.w + sh.w;
    out4[i] = v1;
    out4[i + HALF4] = v2;
}

// ---------------------------------------------------------------------------
extern "C" void kernel_launch(void* const* d_in, const int* in_sizes, int n_in,
                              void* d_out, int out_size) {
    const float* x     = (const float*)d_in[0];
    const int*   idx   = (const int*)  d_in[1];
    const float* Wx    = (const float*)d_in[2];
    const float* bx    = (const float*)d_in[3];
    const float* Wn    = (const float*)d_in[4];
    const float* bn    = (const float*)d_in[5];
    const float* gamma = (const float*)d_in[6];
    const float* beta  = (const float*)d_in[7];
    float* out = (float*)d_out;

    cudaFuncSetAttribute(k_gemm, cudaFuncAttributeMaxDynamicSharedMemorySize,
                         (int)SMEM2);

    float4* xn4;
    cudaGetSymbolAddress((void**)&xn4, g_xn);

    k_gather<<<Mq / 4, 256>>>((const float4*)x, idx, xn4);
    k_gemm<<<Mq / MT, 512, SMEM2>>>(x, Wx, Wn, bx, bn, out);
    k_stats<<<1, Cq>>>(gamma, beta);
    k_apply<<<(int)(HALF4 / 256), 256>>>((float4*)out);
}

// round 5
// speedup vs baseline: 1.0899x; 1.0899x over previous
#include <cuda_runtime.h>
#include <cstdint>
#include <cstddef>

// Problem constants
#define Bq 8
#define Nq 2048
#define Kq 32
#define Fq 256          // F_IN = F_OUT = 256
#define Cq 512          // 2*F_OUT
#define Mq (Bq*Nq)      // 16384 rows

// Scratch (no cudaMalloc allowed)
__device__ float2 g_xp[(size_t)Mq * Fq];   // packed {x, xn}, 32 MB
__device__ float2 g_wp[(size_t)Fq * Fq];   // packed {Wx, Wn}, 512 KB
__device__ float g_sum[Cq];
__device__ float g_sumsq[Cq];
__device__ float4 g_scale4[Cq / 4];
__device__ float4 g_shift4[Cq / 4];

typedef unsigned long long u64;
typedef unsigned int u32;

__device__ __forceinline__ u64 ffma2(u64 a, u64 b, u64 c) {
    u64 d;
    asm("fma.rn.f32x2 %0, %1, %2, %3;" : "=l"(d) : "l"(a), "l"(b), "l"(c));
    return d;
}

// ---------------------------------------------------------------------------
// Kernel 0: interleave weights {Wx, Wn} channel-row-major.
// ---------------------------------------------------------------------------
__global__ __launch_bounds__(256) void k_pack(const float* __restrict__ Wx,
                                              const float* __restrict__ Wn) {
    const int i = blockIdx.x * 256 + threadIdx.x;   // c*256 + k
    g_wp[i] = make_float2(Wx[i], Wn[i]);
}

// ---------------------------------------------------------------------------
// Kernel 1: gather + mean over 32 neighbors; writes packed {x, xn} pairs.
// 4 rows/block, 64 f4-lanes/row. Block 0 zeroes BN accumulators.
// ---------------------------------------------------------------------------
__global__ __launch_bounds__(256) void k_gather(const float4* __restrict__ x4,
                                                const int* __restrict__ idx) {
    if (blockIdx.x == 0) {
        const int c = threadIdx.x;
        g_sum[c] = 0.f;         g_sum[c + 256] = 0.f;
        g_sumsq[c] = 0.f;       g_sumsq[c + 256] = 0.f;
    }
    __shared__ int nbr[4][Kq];
    const int tid = threadIdx.x;
    const int rr = tid >> 6;          // row within block, 0..3
    const int q  = tid & 63;          // float4 lane within row
    const int r  = blockIdx.x * 4 + rr;   // global row = b*N + n
    const int b  = r >> 11;           // N = 2048
    const int n  = r & (Nq - 1);

    if (tid < 128) {
        int k   = tid & 31;
        int rr2 = tid >> 5;
        int n2  = (blockIdx.x * 4 + rr2) & (Nq - 1);
        nbr[rr2][k] = idx[n2 * Kq + k];
    }
    __syncthreads();

    const float4* xb = x4 + (size_t)b * Nq * (Fq / 4);
    float4 acc = make_float4(0.f, 0.f, 0.f, 0.f);
#pragma unroll
    for (int k = 0; k < Kq; k++) {
        float4 v = xb[(size_t)nbr[rr][k] * (Fq / 4) + q];
        acc.x += v.x; acc.y += v.y; acc.z += v.z; acc.w += v.w;
    }
    const float s = 1.f / 32.f;
    const float4 xv = xb[(size_t)n * (Fq / 4) + q];
    float4* dst = (float4*)g_xp + ((size_t)r * 64 + q) * 2;
    dst[0] = make_float4(xv.x, acc.x * s, xv.y, acc.y * s);
    dst[1] = make_float4(xv.z, acc.z * s, xv.w, acc.w * s);
}

// ---------------------------------------------------------------------------
// Kernel 2: dual GEMM (packed f32x2: .x = self, .y = neighbor) + bias
//           + per-row L2 normalize + ReLU + write out + BN stat accumulation.
// Block tile: 64 rows x 256 channel-pairs. 512 threads = 16 warps.
// Warp w: rows (w&7)*8..+8, channel half (w>>3).
// Per thread: 8 rows x 4 pairs in registers (64 acc regs).
// Tiles loaded from pre-packed globals with LDG.128/STS.128.
// ---------------------------------------------------------------------------
#define MT 64
#define KT 32
#define KP 34          // float2 pitch over kk (conflict-free LDS.128)
#define WTILE (256 * KP)   // float2 count of one W tile
#define XTILE (MT * KP)    // float2 count of one X tile
#define SMEM2 ((size_t)(WTILE + XTILE + 2*256) * sizeof(float2) + (MT*2) * sizeof(float))

__global__ __launch_bounds__(512, 1) void k_gemm(const float* __restrict__ bx,
                                                 const float* __restrict__ bn,
                                                 float* __restrict__ out) {
    extern __shared__ char smem_raw[];
    float2* sW   = (float2*)smem_raw;                         // [256][KP]
    float2* sX   = sW + WTILE;                                // [MT][KP]
    float2* redS = sX + XTILE;                                // [256]
    float2* redQ = redS + 256;                                // [256]
    float*  ssb  = (float*)(redQ + 256);                      // [MT][2]

    const int tid  = threadIdx.x;
    const int lane = tid & 31;
    const int w    = tid >> 5;                 // warp id 0..15
    const int wr   = w & 7;                    // row group
    const int wh   = w >> 3;                   // channel half
    const int row0 = blockIdx.x * MT;

    if (tid < 256) {
        redS[tid] = make_float2(0.f, 0.f);
        redQ[tid] = make_float2(0.f, 0.f);
    }

    const int cbase = lane + 128 * wh;         // channel of pair j=0
    const float4* wp4 = (const float4*)g_wp;   // [c][128] float4 (=2 kk each)
    const float4* xp4 = (const float4*)g_xp + (size_t)row0 * 128;

    u64 acc[8][4];
#pragma unroll
    for (int i = 0; i < 8; i++)
#pragma unroll
        for (int j = 0; j < 4; j++) acc[i][j] = 0ull;

    for (int t = 0; t < Fq / KT; t++) {
        const int k4 = t * (KT / 2);           // float4 offset within row
        __syncthreads();                       // prior compute done
        // W tile: 4096 float4, 8 per thread. idx = tid + 512*i.
#pragma unroll
        for (int i = 0; i < 8; i++) {
            const int idx = tid + 512 * i;
            const int c  = idx >> 4;
            const int f4 = idx & 15;           // kk = 2*f4
            *(float4*)(sW + c * KP + 2 * f4) = wp4[c * 128 + k4 + f4];
        }
        // X tile: 1024 float4, 2 per thread.
#pragma unroll
        for (int i = 0; i < 2; i++) {
            const int idx = tid + 512 * i;
            const int m  = idx >> 4;
            const int f4 = idx & 15;
            *(float4*)(sX + m * KP + 2 * f4) = xp4[(size_t)m * 128 + k4 + f4];
        }
        __syncthreads();

#pragma unroll 2
        for (int kk = 0; kk < KT; kk += 2) {
            float4 b4[4];
#pragma unroll
            for (int j = 0; j < 4; j++)
                b4[j] = *(const float4*)(sW + (cbase + 32 * j) * KP + kk);
#pragma unroll
            for (int h = 0; h < 2; h++) {
                float4 a4[4];
#pragma unroll
                for (int i = 0; i < 4; i++)
                    a4[i] = *(const float4*)(sX + (wr * 8 + h * 4 + i) * KP + kk);
#pragma unroll
                for (int i = 0; i < 4; i++) {
                    const u64 alo = ((const u64*)&a4[i])[0];
                    const u64 ahi = ((const u64*)&a4[i])[1];
#pragma unroll
                    for (int j = 0; j < 4; j++) {
                        const u64 blo = ((const u64*)&b4[j])[0];
                        const u64 bhi = ((const u64*)&b4[j])[1];
                        acc[h * 4 + i][j] = ffma2(alo, blo, acc[h * 4 + i][j]);
                        acc[h * 4 + i][j] = ffma2(ahi, bhi, acc[h * 4 + i][j]);
                    }
                }
            }
        }
    }

    // ---- Epilogue ----
    float2 bias[4];
#pragma unroll
    for (int j = 0; j < 4; j++)
        bias[j] = make_float2(bx[cbase + 32 * j], bn[cbase + 32 * j]);

    // Phase 1: bias + per-row partial sum of squares (this warp's 128 pairs)
    float2 v[8][4];
#pragma unroll
    for (int i = 0; i < 8; i++) {
        float ss = 0.f;
#pragma unroll
        for (int j = 0; j < 4; j++) {
            v[i][j] = *(float2*)&acc[i][j];
            v[i][j].x += bias[j].x;
            v[i][j].y += bias[j].y;
            ss += v[i][j].x * v[i][j].x + v[i][j].y * v[i][j].y;
        }
#pragma unroll
        for (int off = 16; off > 0; off >>= 1)
            ss += __shfl_xor_sync(0xffffffffu, ss, off);
        if (lane == 0) ssb[(wr * 8 + i) * 2 + wh] = ss;
    }
    __syncthreads();

    // Phase 2: normalize, relu, store, accumulate stats
    float2 ps[4], pq[4];
#pragma unroll
    for (int j = 0; j < 4; j++) {
        ps[j] = make_float2(0.f, 0.f);
        pq[j] = make_float2(0.f, 0.f);
    }
#pragma unroll
    for (int i = 0; i < 8; i++) {
        const int mr = wr * 8 + i;
        const float sstot = ssb[mr * 2] + ssb[mr * 2 + 1];
        const float rn = 1.f / fmaxf(sqrtf(sstot), 1e-12f);
        float* orow = out + (size_t)(row0 + mr) * Cq;
#pragma unroll
        for (int j = 0; j < 4; j++) {
            float hx = fmaxf(v[i][j].x * rn, 0.f);
            float hn = fmaxf(v[i][j].y * rn, 0.f);
            orow[cbase + 32 * j]       = hx;
            orow[256 + cbase + 32 * j] = hn;
            ps[j].x += hx;      ps[j].y += hn;
            pq[j].x += hx * hx; pq[j].y += hn * hn;
        }
    }

#pragma unroll
    for (int j = 0; j < 4; j++) {
        const int c = cbase + 32 * j;
        atomicAdd(&redS[c].x, ps[j].x);
        atomicAdd(&redS[c].y, ps[j].y);
        atomicAdd(&redQ[c].x, pq[j].x);
        atomicAdd(&redQ[c].y, pq[j].y);
    }
    __syncthreads();
    if (tid < 256) {
        atomicAdd(&g_sum[tid],         redS[tid].x);
        atomicAdd(&g_sum[tid + 256],   redS[tid].y);
        atomicAdd(&g_sumsq[tid],       redQ[tid].x);
        atomicAdd(&g_sumsq[tid + 256], redQ[tid].y);
    }
}

// ---------------------------------------------------------------------------
// Kernel 3: fold BN stats into per-channel scale/shift.
// ---------------------------------------------------------------------------
__global__ void k_stats(const float* __restrict__ gamma,
                        const float* __restrict__ beta) {
    const int c = threadIdx.x;   // 512 threads
    const float inv_n = 1.f / (float)Mq;
    float mu  = g_sum[c] * inv_n;
    float var = fmaxf(g_sumsq[c] * inv_n - mu * mu, 0.f);
    float inv = rsqrtf(var + 1e-5f);
    float sc  = gamma[c] * inv;
    ((float*)g_scale4)[c] = sc;
    ((float*)g_shift4)[c] = beta[c] - mu * sc;
}

// ---------------------------------------------------------------------------
// Kernel 4: apply BN elementwise in place. 2 float4 per thread, half-grid
// apart (same channel slot -> shared scale/shift regs).
// ---------------------------------------------------------------------------
#define HALF4 ((size_t)Mq * (Cq / 4) / 2)    // float4 count of half the output
__global__ __launch_bounds__(256) void k_apply(float4* __restrict__ out4) {
    const size_t i = (size_t)blockIdx.x * blockDim.x + threadIdx.x;
    const int p = (int)(i & 127);         // float4 index within 512-ch row
    const float4 sc = g_scale4[p];
    const float4 sh = g_shift4[p];
    float4 v1 = out4[i];
    float4 v2 = out4[i + HALF4];
    v1.x = v1.x * sc.x + sh.x;  v1.y = v1.y * sc.y + sh.y;
    v1.z = v1.z * sc.z + sh.z;  v1.w = v1.w * sc.w + sh.w;
    v2.x = v2.x * sc.x + sh.x;  v2.y = v2.y * sc.y + sh.y;
    v2.z = v2.z * sc.z + sh.z;  v2.w = v2.w * sc.w + sh.w;
    out4[i] = v1;
    out4[i + HALF4] = v2;
}

// ---------------------------------------------------------------------------
extern "C" void kernel_launch(void* const* d_in, const int* in_sizes, int n_in,
                              void* d_out, int out_size) {
    const float* x     = (const float*)d_in[0];
    const int*   idx   = (const int*)  d_in[1];
    const float* Wx    = (const float*)d_in[2];
    const float* bx    = (const float*)d_in[3];
    const float* Wn    = (const float*)d_in[4];
    const float* bn    = (const float*)d_in[5];
    const float* gamma = (const float*)d_in[6];
    const float* beta  = (const float*)d_in[7];
    float* out = (float*)d_out;

    cudaFuncSetAttribute(k_gemm, cudaFuncAttributeMaxDynamicSharedMemorySize,
                         (int)SMEM2);

    k_pack<<<Fq * Fq / 256, 256>>>(Wx, Wn);
    k_gather<<<Mq / 4, 256>>>((const float4*)x, idx);
    k_gemm<<<Mq / MT, 512, SMEM2>>>(bx, bn, out);
    k_stats<<<1, Cq>>>(gamma, beta);
    k_apply<<<(int)(HALF4 / 256), 256>>>((float4*)out);
}

// round 7
// speedup vs baseline: 1.3487x; 1.2375x over previous
#include <cuda_runtime.h>
#include <cuda_bf16.h>
#include <cstdint>
#include <cstddef>

#define Bq 8
#define Nq 2048
#define Kq 32
#define Fq 256          // F_IN = F_OUT
#define Cq 512          // 2*F_OUT
#define Mq (Bq*Nq)      // 16384 rows

typedef unsigned int u32;
typedef unsigned long long u64;

// Scratch (no cudaMalloc allowed)
__device__ __nv_bfloat16 g_ah[(size_t)Mq * Fq];   // x hi
__device__ __nv_bfloat16 g_al[(size_t)Mq * Fq];   // x lo
__device__ __nv_bfloat16 g_anh[(size_t)Mq * Fq];  // xn hi
__device__ __nv_bfloat16 g_anl[(size_t)Mq * Fq];  // xn lo
__device__ __nv_bfloat16 g_bh[(size_t)Cq * Fq];   // [Wx;Wn] hi, rows=channel
__device__ __nv_bfloat16 g_bl[(size_t)Cq * Fq];   // [Wx;Wn] lo
__device__ float g_sum[Cq];
__device__ float g_sumsq[Cq];

// ---------------------------------------------------------------------------
// helpers
// ---------------------------------------------------------------------------
__device__ __forceinline__ u32 s2u(const void* p) {
    return (u32)__cvta_generic_to_shared(p);
}
__device__ __forceinline__ void cp16(u32 d, const void* g) {
    asm volatile("cp.async.cg.shared.global [%0], [%1], 16;" :: "r"(d), "l"(g));
}
__device__ __forceinline__ void ldmx4(u32* r, u32 a) {
    asm volatile("ldmatrix.sync.aligned.m8n8.x4.shared.b16 {%0,%1,%2,%3}, [%4];"
                 : "=r"(r[0]), "=r"(r[1]), "=r"(r[2]), "=r"(r[3]) : "r"(a));
}
__device__ __forceinline__ void ldmx2(u32* r, u32 a) {
    asm volatile("ldmatrix.sync.aligned.m8n8.x2.shared.b16 {%0,%1}, [%2];"
                 : "=r"(r[0]), "=r"(r[1]) : "r"(a));
}
__device__ __forceinline__ void mma16816(float* d, const u32* a, const u32* b) {
    asm volatile(
        "mma.sync.aligned.m16n8k16.row.col.f32.bf16.bf16.f32 "
        "{%0,%1,%2,%3}, {%4,%5,%6,%7}, {%8,%9}, {%0,%1,%2,%3};"
        : "+f"(d[0]), "+f"(d[1]), "+f"(d[2]), "+f"(d[3])
        : "r"(a[0]), "r"(a[1]), "r"(a[2]), "r"(a[3]), "r"(b[0]), "r"(b[1]));
}
__device__ __forceinline__ uint2 pack4(float a, float b, float c, float d) {
    __nv_bfloat162 lo = __floats2bfloat162_rn(a, b);
    __nv_bfloat162 hi = __floats2bfloat162_rn(c, d);
    uint2 r;
    r.x = *reinterpret_cast<u32*>(&lo);
    r.y = *reinterpret_cast<u32*>(&hi);
    return r;
}

// ---------------------------------------------------------------------------
// Kernel 1: gather+mean, hi/lo bf16 split of x and xn; weight pack (blocks<512);
// block 0 zeroes BN stat accumulators.
// ---------------------------------------------------------------------------
__global__ __launch_bounds__(256) void k_gather(const float4* __restrict__ x4,
                                                const int* __restrict__ idx,
                                                const float* __restrict__ Wx,
                                                const float* __restrict__ Wn) {
    const int tid = threadIdx.x;
    if (blockIdx.x == 0) {
        g_sum[tid] = 0.f;   g_sum[tid + 256] = 0.f;
        g_sumsq[tid] = 0.f; g_sumsq[tid + 256] = 0.f;
    }
    if (blockIdx.x < Cq) {    // weight pack: channel = blockIdx, k = tid
        const int c = blockIdx.x;
        float wv = (c < 256) ? Wx[c * Fq + tid] : Wn[(c - 256) * Fq + tid];
        __nv_bfloat16 h = __float2bfloat16(wv);
        g_bh[c * Fq + tid] = h;
        g_bl[c * Fq + tid] = __float2bfloat16(wv - __bfloat162float(h));
    }
    __shared__ int nbr[4][Kq];
    const int rr = tid >> 6;
    const int q  = tid & 63;
    const int r  = blockIdx.x * 4 + rr;
    const int b  = r >> 11;
    const int n  = r & (Nq - 1);

    if (tid < 128) {
        int k   = tid & 31;
        int rr2 = tid >> 5;
        int n2  = (blockIdx.x * 4 + rr2) & (Nq - 1);
        nbr[rr2][k] = idx[n2 * Kq + k];
    }
    __syncthreads();

    const float4* xb = x4 + (size_t)b * Nq * (Fq / 4);
    float4 acc = make_float4(0.f, 0.f, 0.f, 0.f);
#pragma unroll
    for (int k = 0; k < Kq; k++) {
        float4 v = xb[(size_t)nbr[rr][k] * (Fq / 4) + q];
        acc.x += v.x; acc.y += v.y; acc.z += v.z; acc.w += v.w;
    }
    const float s = 1.f / 32.f;
    acc.x *= s; acc.y *= s; acc.z *= s; acc.w *= s;
    const float4 xv = xb[(size_t)n * (Fq / 4) + q];

    const size_t o = (size_t)r * Fq + 4 * q;
    float h0, h1, h2, h3;
    h0 = __bfloat162float(__float2bfloat16(xv.x));
    h1 = __bfloat162float(__float2bfloat16(xv.y));
    h2 = __bfloat162float(__float2bfloat16(xv.z));
    h3 = __bfloat162float(__float2bfloat16(xv.w));
    *(uint2*)(g_ah + o) = pack4(h0, h1, h2, h3);
    *(uint2*)(g_al + o) = pack4(xv.x - h0, xv.y - h1, xv.z - h2, xv.w - h3);
    h0 = __bfloat162float(__float2bfloat16(acc.x));
    h1 = __bfloat162float(__float2bfloat16(acc.y));
    h2 = __bfloat162float(__float2bfloat16(acc.z));
    h3 = __bfloat162float(__float2bfloat16(acc.w));
    *(uint2*)(g_anh + o) = pack4(h0, h1, h2, h3);
    *(uint2*)(g_anl + o) = pack4(acc.x - h0, acc.y - h1, acc.z - h2, acc.w - h3);
}

// ---------------------------------------------------------------------------
// Kernel 2: mma.sync bf16 dual GEMM, 3-term hi/lo fp32 emulation, fused
// bias / row L2-norm / ReLU / BN-stat epilogue.
// CTA: 64 rows x 512 channels, 256 threads (8 warps).
// Warp (wr = w>>2, wc = w&3): rows wr*32..+32, channels wc*128..+128.
// wc<2 -> A = x (self channels), wc>=2 -> A = xn (neighbor channels).
// K pipeline: 16 steps of k16, double-buffered 16B cp.async.
// ---------------------------------------------------------------------------
#define APITCH 48                 // bytes per 16-bf16 row (32B data + pad)
#define AOFF  3072                // per A-array tile bytes (64*48)
#define BOFF  24576               // per B-array tile bytes (512*48)
#define STAGE_SZ (4*AOFF + 2*BOFF)   // 61440
#define SM_TILES 3584             // tiles (and epi staging) start here
#define EPITCH 516                // epilogue staging pitch (floats)
#define SMEMM (SM_TILES + 64*EPITCH*4)   // 135680 (>= tiles: 3584+2*61440=126464)

__global__ __launch_bounds__(256, 1) void k_mma(const float* __restrict__ bx,
                                                const float* __restrict__ bn,
                                                float* __restrict__ out) {
    extern __shared__ char sm[];
    float* sbias = (float*)sm;            // [512]
    float* ssqp  = (float*)(sm + 2048);   // [64][4]
    float* rinv  = (float*)(sm + 3072);   // [64]

    const int tid  = threadIdx.x;
    const int lane = tid & 31;
    const int w    = tid >> 5;
    const int wr   = w >> 2;              // row half
    const int wc   = w & 3;               // channel quarter
    const int row0 = blockIdx.x * 64;

    sbias[tid] = bx[tid];  sbias[tid + 256] = bn[tid];

    // ---- async tile loader ----
    auto issue = [&](int kt, int st) {
        const u32 sb = s2u(sm) + SM_TILES + st * STAGE_SZ;
        const int ko = kt * 16;
        // A: arrays {xh, xl, nh, nl}; 128 16B-chunks each; 2 per thread.
#pragma unroll
        for (int i = 0; i < 2; i++) {
            const int hiarr = tid >> 7;              // 0: hi, 1: lo
            const int arr   = i * 2 + hiarr;         // 0 xh,1 xl,2 nh,3 nl
            const int idx2  = tid & 127;
            const int r  = idx2 >> 1;
            const int hf = idx2 & 1;
            const __nv_bfloat16* gp =
                (i == 0) ? (hiarr ? g_al : g_ah) : (hiarr ? g_anl : g_anh);
            cp16(sb + arr * AOFF + r * APITCH + hf * 16,
                 gp + (size_t)(row0 + r) * Fq + ko + hf * 8);
        }
        // B: arrays {bh, bl}; 1024 chunks each; 8 per thread (arr = i>>2).
#pragma unroll
        for (int i = 0; i < 8; i++) {
            const int b2 = tid + 256 * i;
            const int arr = i >> 2;
            const int idx2 = b2 & 1023;
            const int c  = idx2 >> 1;
            const int hf = idx2 & 1;
            const __nv_bfloat16* gp = arr ? g_bl : g_bh;
            cp16(sb + 4 * AOFF + arr * BOFF + c * APITCH + hf * 16,
                 gp + (size_t)c * Fq + ko + hf * 8);
        }
        asm volatile("cp.async.commit_group;");
    };

    float acc[2][16][4];
#pragma unroll
    for (int mt = 0; mt < 2; mt++)
#pragma unroll
        for (int tn = 0; tn < 16; tn++)
#pragma unroll
            for (int k = 0; k < 4; k++) acc[mt][tn][k] = 0.f;

    issue(0, 0);
    issue(1, 1);

    const int arow   = (lane & 7) + ((lane >> 3) & 1) * 8;
    const int acol16 = (lane >> 4) * 16;
    const int brow   = lane & 7;
    const int bcol16 = ((lane >> 3) & 1) * 16;

    for (int kt = 0; kt < 16; kt++) {
        if (kt < 15) asm volatile("cp.async.wait_group 1;");
        else         asm volatile("cp.async.wait_group 0;");
        __syncthreads();

        const int st = kt & 1;
        const u32 sb = s2u(sm) + SM_TILES + st * STAGE_SZ;
        const u32 ab = sb + ((wc >= 2) ? 2 * AOFF : 0);   // xh or nh
        const u32 bb = sb + 4 * AOFF;

        u32 ahi[2][4], alo[2][4];
#pragma unroll
        for (int mt = 0; mt < 2; mt++) {
            const u32 ad = ab + (wr * 32 + mt * 16 + arow) * APITCH + acol16;
            ldmx4(ahi[mt], ad);
            ldmx4(alo[mt], ad + AOFF);
        }
#pragma unroll
        for (int nc = 0; nc < 4; nc++) {
            u32 bhf[4][2], blf[4][2];
#pragma unroll
            for (int j = 0; j < 4; j++) {
                const int ch = wc * 128 + (nc * 4 + j) * 8;
                const u32 bd = bb + (ch + brow) * APITCH + bcol16;
                ldmx2(bhf[j], bd);
                ldmx2(blf[j], bd + BOFF);
            }
#pragma unroll
            for (int mt = 0; mt < 2; mt++)
#pragma unroll
                for (int j = 0; j < 4; j++) {
                    float* d = acc[mt][nc * 4 + j];
                    mma16816(d, ahi[mt], bhf[j]);
                    mma16816(d, ahi[mt], blf[j]);
                    mma16816(d, alo[mt], bhf[j]);
                }
        }

        if (kt < 14) {
            __syncthreads();           // all warps done reading stage st
            issue(kt + 2, st);
        }
    }
    __syncthreads();

    // ---- Epilogue: stage bias-added accums to smem [64][EPITCH] ----
    float* sg = (float*)(sm + SM_TILES);
#pragma unroll
    for (int mt = 0; mt < 2; mt++) {
        const int re = wr * 32 + mt * 16 + (lane >> 2);
#pragma unroll
        for (int tn = 0; tn < 16; tn++) {
            const int col = wc * 128 + tn * 8 + 2 * (lane & 3);
            const float2 bv = *(float2*)&sbias[col];
            float* p0 = &sg[re * EPITCH + col];
            p0[0] = acc[mt][tn][0] + bv.x;
            p0[1] = acc[mt][tn][1] + bv.y;
            float* p1 = &sg[(re + 8) * EPITCH + col];
            p1[0] = acc[mt][tn][2] + bv.x;
            p1[1] = acc[mt][tn][3] + bv.y;
        }
    }
    __syncthreads();

    // row sum-of-squares: thread -> (row = tid>>2, quarter = tid&3)
    {
        const int r = tid >> 2, q = tid & 3;
        const float4* rp = (const float4*)&sg[r * EPITCH + q * 128];
        float s = 0.f;
#pragma unroll
        for (int i = 0; i < 32; i++) {
            float4 v = rp[i];
            s += v.x * v.x + v.y * v.y + v.z * v.z + v.w * v.w;
        }
        ssqp[r * 4 + q] = s;
    }
    __syncthreads();
    if (tid < 64) {
        const float s = ssqp[tid * 4] + ssqp[tid * 4 + 1]
                      + ssqp[tid * 4 + 2] + ssqp[tid * 4 + 3];
        rinv[tid] = 1.f / fmaxf(sqrtf(s), 1e-12f);
    }
    __syncthreads();

    // normalize + relu + store + BN stats. thread: c4 = tid&127, rh = tid>>7.
    {
        const int c4 = tid & 127;
        const int rh = tid >> 7;
        float s0 = 0.f, s1 = 0.f, s2 = 0.f, s3 = 0.f;
        float q0 = 0.f, q1 = 0.f, q2 = 0.f, q3 = 0.f;
#pragma unroll 4
        for (int i = 0; i < 32; i++) {
            const int r = rh * 32 + i;
            float4 v = *(float4*)&sg[r * EPITCH + c4 * 4];
            const float rv = rinv[r];
            v.x = fmaxf(v.x * rv, 0.f); v.y = fmaxf(v.y * rv, 0.f);
            v.z = fmaxf(v.z * rv, 0.f); v.w = fmaxf(v.w * rv, 0.f);
            *(float4*)(out + (size_t)(row0 + r) * Cq + c4 * 4) = v;
            s0 += v.x; s1 += v.y; s2 += v.z; s3 += v.w;
            q0 += v.x * v.x; q1 += v.y * v.y; q2 += v.z * v.z; q3 += v.w * v.w;
        }
        atomicAdd(&g_sum[c4 * 4 + 0], s0);  atomicAdd(&g_sum[c4 * 4 + 1], s1);
        atomicAdd(&g_sum[c4 * 4 + 2], s2);  atomicAdd(&g_sum[c4 * 4 + 3], s3);
        atomicAdd(&g_sumsq[c4 * 4 + 0], q0); atomicAdd(&g_sumsq[c4 * 4 + 1], q1);
        atomicAdd(&g_sumsq[c4 * 4 + 2], q2); atomicAdd(&g_sumsq[c4 * 4 + 3], q3);
    }
}

// ---------------------------------------------------------------------------
// Kernel 3: per-block BN fold (stats -> scale/shift in smem) + apply.
// ---------------------------------------------------------------------------
#define HALF4 ((size_t)Mq * (Cq / 4) / 2)
__global__ __launch_bounds__(256) void k_apply(float4* __restrict__ out4,
                                               const float* __restrict__ gamma,
                                               const float* __restrict__ beta) {
    __shared__ float sc[Cq], sh[Cq];
    const int t = threadIdx.x;
    const float inv_n = 1.f / (float)Mq;
#pragma unroll
    for (int o = 0; o < 2; o++) {
        const int c = t + 256 * o;
        float mu  = g_sum[c] * inv_n;
        float var = fmaxf(g_sumsq[c] * inv_n - mu * mu, 0.f);
        float iv  = rsqrtf(var + 1e-5f);
        float s   = gamma[c] * iv;
        sc[c] = s;
        sh[c] = beta[c] - mu * s;
    }
    __syncthreads();
    const size_t i = (size_t)blockIdx.x * 256 + t;
    const int p = (int)(i & 127) * 4;
    const float4 s4 = *(float4*)&sc[p];
    const float4 h4 = *(float4*)&sh[p];
    float4 v1 = out4[i];
    float4 v2 = out4[i + HALF4];
    v1.x = v1.x * s4.x + h4.x;  v1.y = v1.y * s4.y + h4.y;
    v1.z = v1.z * s4.z + h4.z;  v1.w = v1.w * s4.w + h4.w;
    v2.x = v2.x * s4.x + h4.x;  v2.y = v2.y * s4.y + h4.y;
    v2.z = v2.z * s4.z + h4.z;  v2.w = v2.w * s4.w + h4.w;
    out4[i] = v1;
    out4[i + HALF4] = v2;
}

// ---------------------------------------------------------------------------
extern "C" void kernel_launch(void* const* d_in, const int* in_sizes, int n_in,
                              void* d_out, int out_size) {
    const float* x     = (const float*)d_in[0];
    const int*   idx   = (const int*)  d_in[1];
    const float* Wx    = (const float*)d_in[2];
    const float* bx    = (const float*)d_in[3];
    const float* Wn    = (const float*)d_in[4];
    const float* bn    = (const float*)d_in[5];
    const float* gamma = (const float*)d_in[6];
    const float* beta  = (const float*)d_in[7];
    float* out = (float*)d_out;

    cudaFuncSetAttribute(k_mma, cudaFuncAttributeMaxDynamicSharedMemorySize,
                         SMEMM);

    k_gather<<<Mq / 4, 256>>>((const float4*)x, idx, Wx, Wn);
    k_mma<<<Mq / 64, 256, SMEMM>>>(bx, bn, out);
    k_apply<<<(int)(HALF4 / 256), 256>>>((float4*)out, gamma, beta);
}